// round 8
// baseline (speedup 1.0000x reference)
#include <cuda_runtime.h>

// SSIM, 7x7 VALID box, 128 x 384x384 fp32 pairs -> scalar mean.
//
// v8: v7's ILP-2 packed-f32x2 pipeline + occupancy push.
//  - 14 row-bands of 27 (7168 warps) for ~48 warps/SM of demand.
//  - __launch_bounds__(128, 9) caps regs at 56 -> 36-warp/SM reg ceiling.
//  - Peeled epilogue (rows 24,25,26) so the hot loop has no clamps and
//    no OOB (max input row touched = r0+32 <= 383).

#define IMG_H 384
#define IMG_W 384
#define OUT_W 378
#define OUT_H 378
#define NIMG  128
#define NSTRIP 4
#define NBAND  14
#define BAND_OUT 27
#define NIT   12                                  // double-row iterations
#define WARPS_PER_CTA 4
#define WARPS_TOTAL (NIMG * NSTRIP * NBAND)       // 7168
#define NCTA (WARPS_TOTAL / WARPS_PER_CTA)        // 1792

__device__ float g_cta[NCTA];
__device__ unsigned int g_done = 0;

typedef unsigned long long u64;
static __device__ __forceinline__ u64 pk2(float lo, float hi) {
    u64 r; asm("mov.b64 %0,{%1,%2};" : "=l"(r) : "f"(lo), "f"(hi)); return r;
}
static __device__ __forceinline__ void upk2(float& lo, float& hi, u64 v) {
    asm("mov.b64 {%0,%1},%2;" : "=f"(lo), "=f"(hi) : "l"(v));
}
static __device__ __forceinline__ u64 add2(u64 a, u64 b) {
    u64 d; asm("add.rn.f32x2 %0,%1,%2;" : "=l"(d) : "l"(a), "l"(b)); return d;
}
static __device__ __forceinline__ u64 mul2(u64 a, u64 b) {
    u64 d; asm("mul.rn.f32x2 %0,%1,%2;" : "=l"(d) : "l"(a), "l"(b)); return d;
}
static __device__ __forceinline__ u64 fma2(u64 a, u64 b, u64 c) {
    u64 d; asm("fma.rn.f32x2 %0,%1,%2,%3;" : "=l"(d) : "l"(a), "l"(b), "l"(c)); return d;
}
static __device__ __forceinline__ u64 neg2(u64 a) {
    return a ^ 0x8000000080000000ULL;
}

#define HPACK(q01, q23, Wlo, Whi)                                          \
    {                                                                      \
        float v0, v1, v2, v3;                                              \
        upk2(v0, v1, q01); upk2(v2, v3, q23);                              \
        float v4 = __shfl_down_sync(0xffffffffu, v0, 1);                   \
        float v5 = __shfl_down_sync(0xffffffffu, v1, 1);                   \
        float v6 = __shfl_down_sync(0xffffffffu, v2, 1);                   \
        float v7 = __shfl_down_sync(0xffffffffu, v3, 1);                   \
        float v8 = __shfl_down_sync(0xffffffffu, v0, 2);                   \
        float v9 = __shfl_down_sync(0xffffffffu, v1, 2);                   \
        u64 E2 = pk2(v4, v5), E3 = pk2(v6, v7), E4 = pk2(v8, v9);          \
        u64 D0 = pk2(v1, v2), D1 = pk2(v3, v4);                            \
        u64 D2 = pk2(v5, v6), D3 = pk2(v7, v8);                            \
        u64 SE = add2(q23, add2(E2, E3));                                  \
        u64 SD = add2(D1, D2);                                             \
        Wlo = add2(add2(q01, SE), add2(D0, SD));                           \
        Whi = add2(add2(SE, E4), add2(SD, D3));                            \
    }

#define ADMIT(a4, b4)                                                      \
    {                                                                      \
        u64 ax01 = pk2((a4).x, (a4).y), ax23 = pk2((a4).z, (a4).w);        \
        u64 ay01 = pk2((b4).x, (b4).y), ay23 = pk2((b4).z, (b4).w);        \
        X01 = add2(X01, ax01);  X23 = add2(X23, ax23);                     \
        Y01 = add2(Y01, ay01);  Y23 = add2(Y23, ay23);                     \
        Z01 = fma2(ax01, ax01, fma2(ay01, ay01, Z01));                     \
        Z23 = fma2(ax23, ax23, fma2(ay23, ay23, Z23));                     \
        XY01 = fma2(ax01, ay01, XY01);  XY23 = fma2(ax23, ay23, XY23);     \
    }

#define RETIRE(a4, b4)                                                     \
    {                                                                      \
        u64 ox01 = pk2((a4).x, (a4).y), ox23 = pk2((a4).z, (a4).w);        \
        u64 oy01 = pk2((b4).x, (b4).y), oy23 = pk2((b4).z, (b4).w);        \
        u64 nx01 = neg2(ox01), nx23 = neg2(ox23);                          \
        u64 ny01 = neg2(oy01), ny23 = neg2(oy23);                          \
        X01 = add2(X01, nx01);  X23 = add2(X23, nx23);                     \
        Y01 = add2(Y01, ny01);  Y23 = add2(Y23, ny23);                     \
        Z01 = fma2(ox01, nx01, fma2(oy01, ny01, Z01));                     \
        Z23 = fma2(ox23, nx23, fma2(oy23, ny23, Z23));                     \
        XY01 = fma2(ox01, ny01, XY01);  XY23 = fma2(ox23, ny23, XY23);     \
    }

#define SSIM_HALF(WX, WY, WZ, WXY, mask, accR)                             \
    {                                                                      \
        u64 p01 = mul2(WX, WY);                                            \
        u64 p00 = mul2(WX, WX);                                            \
        u64 p11 = mul2(WY, WY);                                            \
        u64 tt  = add2(p00, p11);                                          \
        u64 Axy = fma2(p01, c_ns1, WXY);                                   \
        u64 AB  = fma2(tt,  c_ns1, WZ);                                    \
        u64 n1  = fma2(p01, c_kn1, c_C1);                                  \
        u64 n2  = fma2(Axy, c_kc2, c_C2);                                  \
        u64 d1  = fma2(tt,  c_ks2, c_C1);                                  \
        u64 d2  = fma2(AB,  c_kcv, c_C2);                                  \
        u64 num = mul2(n1, n2);                                            \
        u64 den = mul2(d1, d2);                                            \
        float na, nb, da, db;                                              \
        upk2(na, nb, num); upk2(da, db, den);                              \
        u64 rr = pk2(__fdividef(na, da), __fdividef(nb, db));              \
        accR = fma2(mask, rr, accR);                                       \
    }

#define DO_ROW()                                                           \
    {                                                                      \
        u64 WXl, WXh, WYl, WYh, WZl, WZh, WXYl, WXYh;                      \
        HPACK(X01,  X23,  WXl,  WXh);                                      \
        HPACK(Y01,  Y23,  WYl,  WYh);                                      \
        HPACK(Z01,  Z23,  WZl,  WZh);                                      \
        HPACK(XY01, XY23, WXYl, WXYh);                                     \
        SSIM_HALF(WXl, WYl, WZl, WXYl, m01, accA);                         \
        SSIM_HALF(WXh, WYh, WZh, WXYh, m23, accB);                         \
    }

__global__ __launch_bounds__(WARPS_PER_CTA * 32, 9)
void ssim_v8_kernel(const float* __restrict__ pred,
                    const float* __restrict__ actual,
                    float* __restrict__ out) {
    const int gtid = blockIdx.x * blockDim.x + threadIdx.x;
    const int W    = gtid >> 5;
    const int lane = gtid & 31;
    const int wid  = threadIdx.x >> 5;

    const int img   = W / (NSTRIP * NBAND);
    const int rem   = W - img * (NSTRIP * NBAND);
    const int band  = rem / NSTRIP;
    const int strip = rem - band * NSTRIP;

    // strips: [0,96) [96,192) [192,284) [284,378)
    int base = strip * 96;          if (strip == 3) base = 284;
    int send = base + 96;           if (strip == 2) send = 284;
    if (strip == 3) send = 378;

    int cs = base + 4 * lane;
    if (cs > IMG_W - 4) cs = IMG_W - 4;

    const int r0 = band * BAND_OUT;                 // max 351; r0+32 <= 383

    const int oc = base + 4 * lane;
    const u64 m01 = pk2((oc + 0 < send) ? 1.f : 0.f, (oc + 1 < send) ? 1.f : 0.f);
    const u64 m23 = pk2((oc + 2 < send) ? 1.f : 0.f, (oc + 3 < send) ? 1.f : 0.f);

    const float* pX = pred   + (size_t)img * IMG_H * IMG_W + (size_t)r0 * IMG_W + cs;
    const float* pY = actual + (size_t)img * IMG_H * IMG_W + (size_t)r0 * IMG_W + cs;

    u64 X01 = 0, X23 = 0, Y01 = 0, Y23 = 0;
    u64 Z01 = 0, Z23 = 0, XY01 = 0, XY23 = 0;

    // prologue: rows 0..5
    #pragma unroll 1
    for (int k = 0; k < 6; ++k) {
        float4 a = *(const float4*)(pX + (size_t)k * IMG_W);
        float4 b = *(const float4*)(pY + (size_t)k * IMG_W);
        ADMIT(a, b);
    }

    // prefetch rows 6, 7
    float4 pfAx = *(const float4*)(pX + (size_t)6 * IMG_W);
    float4 pfAy = *(const float4*)(pY + (size_t)6 * IMG_W);
    float4 pfBx = *(const float4*)(pX + (size_t)7 * IMG_W);
    float4 pfBy = *(const float4*)(pY + (size_t)7 * IMG_W);

    const float s1   = 1.0f / 49.0f;
    const float covn = 49.0f / 48.0f;
    const u64 c_ns1 = pk2(-s1, -s1);
    const u64 c_kn1 = pk2(2.f * s1 * s1, 2.f * s1 * s1);
    const u64 c_ks2 = pk2(s1 * s1, s1 * s1);
    const u64 c_kcv = pk2(covn * s1, covn * s1);
    const u64 c_kc2 = pk2(2.f * covn * s1, 2.f * covn * s1);
    const u64 c_C1  = pk2(1e-4f, 1e-4f);
    const u64 c_C2  = pk2(9e-4f, 9e-4f);

    u64 accA = 0, accB = 0;

    // 12 double-row iterations: output rows 0..23.
    // Loads per iter: retire rows 2it, 2it+1; prefetch rows 2it+8, 2it+9 (max 31).
    #pragma unroll 1
    for (int it = 0; it < NIT; ++it) {
        float4 rt0x = *(const float4*)(pX);
        float4 rt0y = *(const float4*)(pY);
        float4 rt1x = *(const float4*)(pX + IMG_W);
        float4 rt1y = *(const float4*)(pY + IMG_W);

        ADMIT(pfAx, pfAy);
        DO_ROW();
        RETIRE(rt0x, rt0y);
        ADMIT(pfBx, pfBy);
        DO_ROW();
        RETIRE(rt1x, rt1y);

        pfAx = *(const float4*)(pX + (size_t)8 * IMG_W);
        pfAy = *(const float4*)(pY + (size_t)8 * IMG_W);
        pfBx = *(const float4*)(pX + (size_t)9 * IMG_W);
        pfBy = *(const float4*)(pY + (size_t)9 * IMG_W);

        pX += 2 * IMG_W;  pY += 2 * IMG_W;
    }
    // epilogue: rows 24, 25, 26 (pX now at row 24; pfA=row30, pfB=row31)
    {
        float4 rt0x = *(const float4*)(pX);
        float4 rt0y = *(const float4*)(pY);
        float4 rt1x = *(const float4*)(pX + IMG_W);
        float4 rt1y = *(const float4*)(pY + IMG_W);
        float4 lx32 = *(const float4*)(pX + (size_t)8 * IMG_W);   // row 32
        float4 ly32 = *(const float4*)(pY + (size_t)8 * IMG_W);

        ADMIT(pfAx, pfAy);          // window rows 24..30 -> output row 24
        DO_ROW();
        RETIRE(rt0x, rt0y);
        ADMIT(pfBx, pfBy);          // window rows 25..31 -> output row 25
        DO_ROW();
        RETIRE(rt1x, rt1y);
        ADMIT(lx32, ly32);          // window rows 26..32 -> output row 26
        DO_ROW();
    }

    // lane-local total, deterministic warp reduction
    float a0, a1, b0, b1;
    upk2(a0, a1, accA); upk2(b0, b1, accB);
    float acc = (a0 + a1) + (b0 + b1);
    #pragma unroll
    for (int off = 16; off > 0; off >>= 1)
        acc += __shfl_xor_sync(0xffffffffu, acc, off);

    // CTA reduction (deterministic order)
    __shared__ float warp_sums[WARPS_PER_CTA];
    __shared__ unsigned int s_last;
    if (lane == 0) warp_sums[wid] = acc;
    __syncthreads();
    if (threadIdx.x == 0) {
        float c = 0.f;
        #pragma unroll
        for (int i = 0; i < WARPS_PER_CTA; ++i) c += warp_sums[i];
        g_cta[blockIdx.x] = c;
        __threadfence();
        unsigned int old = atomicAdd(&g_done, 1u);
        s_last = (old == NCTA - 1) ? 1u : 0u;
    }
    __syncthreads();

    // last CTA: deterministic fixed-order reduction of 1792 partials
    if (s_last) {
        __shared__ float red[128];
        const int t = threadIdx.x;
        float c = 0.f;
        #pragma unroll
        for (int i = 0; i < NCTA / 128; ++i)      // 14 slots, fixed order
            c += g_cta[t + i * 128];
        red[t] = c;
        __syncthreads();
        #pragma unroll
        for (int s = 64; s > 0; s >>= 1) {
            if (t < s) red[t] += red[t + s];
            __syncthreads();
        }
        if (t == 0) {
            out[0] = red[0] * (1.0f / ((float)NIMG * (float)OUT_W * (float)OUT_H));
            g_done = 0;   // reset for graph replay
        }
    }
}

extern "C" void kernel_launch(void* const* d_in, const int* in_sizes, int n_in,
                              void* d_out, int out_size) {
    const float* pred   = (const float*)d_in[0];
    const float* actual = (const float*)d_in[1];
    float* out = (float*)d_out;

    ssim_v8_kernel<<<NCTA, WARPS_PER_CTA * 32>>>(pred, actual, out);
}

// round 9
// speedup vs baseline: 1.4927x; 1.4927x over previous
#include <cuda_runtime.h>

// SSIM, 7x7 VALID box, 128 x 384x384 fp32 pairs -> scalar mean.
//
// v9: full-row warps, 12 columns per lane.
//  - Warp covers the whole 384-col row; lane l owns cols 12l..12l+11.
//  - Vertical sliding sums packed f32x2 (6 u64 per quantity; Z = XX+YY).
//  - Horizontal 7-sums by running difference: W0 = 6 adds, then
//    W_{t+1} = W_t + (v_{t+7} - v_t); only 6 SHFL/quantity per row
//    (neighbor tail), vs 24+ in the strip design.
//  - SSIM on packed output pairs; lane 31's upper half masked (garbage
//    there is sums of real pixels -> denominator > 0, mask-safe).
//  - 14 bands x 27 rows, 64-thread CTAs, one wave; deterministic
//    single-kernel last-CTA reduction.

#define IMG_H 384
#define IMG_W 384
#define OUT_W 378
#define OUT_H 378
#define NIMG  128
#define NBAND 14
#define BAND_OUT 27
#define NTHREADS 64
#define WARPS_TOTAL (NIMG * NBAND)        // 1792
#define NCTA (WARPS_TOTAL / 2)            // 896

__device__ float g_cta[NCTA];
__device__ unsigned int g_done = 0;

typedef unsigned long long u64;
static __device__ __forceinline__ u64 pk2(float lo, float hi) {
    u64 r; asm("mov.b64 %0,{%1,%2};" : "=l"(r) : "f"(lo), "f"(hi)); return r;
}
static __device__ __forceinline__ void upk2(float& lo, float& hi, u64 v) {
    asm("mov.b64 {%0,%1},%2;" : "=f"(lo), "=f"(hi) : "l"(v));
}
static __device__ __forceinline__ u64 add2(u64 a, u64 b) {
    u64 d; asm("add.rn.f32x2 %0,%1,%2;" : "=l"(d) : "l"(a), "l"(b)); return d;
}
static __device__ __forceinline__ u64 mul2(u64 a, u64 b) {
    u64 d; asm("mul.rn.f32x2 %0,%1,%2;" : "=l"(d) : "l"(a), "l"(b)); return d;
}
static __device__ __forceinline__ u64 fma2(u64 a, u64 b, u64 c) {
    u64 d; asm("fma.rn.f32x2 %0,%1,%2,%3;" : "=l"(d) : "l"(a), "l"(b), "l"(c)); return d;
}
static __device__ __forceinline__ u64 neg2(u64 a) {
    return a ^ 0x8000000080000000ULL;
}

// vertical admit / retire over one row (6 float4 = 12 cols x 2 images)
#define ADMIT6(x0,x1,x2,y0,y1,y2) {                                         \
    u64 px[6] = { pk2((x0).x,(x0).y), pk2((x0).z,(x0).w),                   \
                  pk2((x1).x,(x1).y), pk2((x1).z,(x1).w),                   \
                  pk2((x2).x,(x2).y), pk2((x2).z,(x2).w) };                 \
    u64 py[6] = { pk2((y0).x,(y0).y), pk2((y0).z,(y0).w),                   \
                  pk2((y1).x,(y1).y), pk2((y1).z,(y1).w),                   \
                  pk2((y2).x,(y2).y), pk2((y2).z,(y2).w) };                 \
    _Pragma("unroll")                                                       \
    for (int _i = 0; _i < 6; ++_i) {                                        \
        X[_i]  = add2(X[_i],  px[_i]);                                      \
        Y[_i]  = add2(Y[_i],  py[_i]);                                      \
        Z[_i]  = fma2(px[_i], px[_i], fma2(py[_i], py[_i], Z[_i]));         \
        XY[_i] = fma2(px[_i], py[_i], XY[_i]);                              \
    } }

#define RETIRE6(x0,x1,x2,y0,y1,y2) {                                        \
    u64 px[6] = { pk2((x0).x,(x0).y), pk2((x0).z,(x0).w),                   \
                  pk2((x1).x,(x1).y), pk2((x1).z,(x1).w),                   \
                  pk2((x2).x,(x2).y), pk2((x2).z,(x2).w) };                 \
    u64 py[6] = { pk2((y0).x,(y0).y), pk2((y0).z,(y0).w),                   \
                  pk2((y1).x,(y1).y), pk2((y1).z,(y1).w),                   \
                  pk2((y2).x,(y2).y), pk2((y2).z,(y2).w) };                 \
    _Pragma("unroll")                                                       \
    for (int _i = 0; _i < 6; ++_i) {                                        \
        u64 nx = neg2(px[_i]), ny = neg2(py[_i]);                           \
        X[_i]  = add2(X[_i],  nx);                                          \
        Y[_i]  = add2(Y[_i],  ny);                                          \
        Z[_i]  = fma2(px[_i], nx, fma2(py[_i], ny, Z[_i]));                 \
        XY[_i] = fma2(px[_i], ny, XY[_i]);                                  \
    } }

// SSIM on one packed output pair
#define SSIM_PAIR(WXp, WYp, WZp, WXYp, mask, accR) {                        \
    u64 p01 = mul2(WXp, WYp);                                               \
    u64 p00 = mul2(WXp, WXp);                                               \
    u64 p11 = mul2(WYp, WYp);                                               \
    u64 tt  = add2(p00, p11);                                               \
    u64 Axy = fma2(p01, c_ns1, WXYp);                                       \
    u64 AB  = fma2(tt,  c_ns1, WZp);                                        \
    u64 n1  = fma2(p01, c_kn1, c_C1);                                       \
    u64 n2  = fma2(Axy, c_kc2, c_C2);                                       \
    u64 d1  = fma2(tt,  c_ks2, c_C1);                                       \
    u64 d2  = fma2(AB,  c_kcv, c_C2);                                       \
    u64 num = mul2(n1, n2);                                                 \
    u64 den = mul2(d1, d2);                                                 \
    float na, nb, da, db;                                                   \
    upk2(na, nb, num); upk2(da, db, den);                                   \
    u64 rr = pk2(__fdividef(na, da), __fdividef(nb, db));                   \
    accR = fma2(mask, rr, accR); }

// advance the 4 running sums: n* = c* + (v[iTo] - v[iFrom])
#define ADV_N(iTo, iFrom)                                                   \
    nx = cx + (xv[iTo]-xv[iFrom]); ny = cy + (yv[iTo]-yv[iFrom]);           \
    nz = cz + (zv[iTo]-zv[iFrom]); nw = cw + (wv[iTo]-wv[iFrom]);
#define ADV_C(iTo, iFrom)                                                   \
    cx = nx + (xv[iTo]-xv[iFrom]); cy = ny + (yv[iTo]-yv[iFrom]);           \
    cz = nz + (zv[iTo]-zv[iFrom]); cw = nw + (wv[iTo]-wv[iFrom]);
#define ADV_NU(j, iFrom)                                                    \
    nx = cx + (xu[j]-xv[iFrom]); ny = cy + (yu[j]-yv[iFrom]);               \
    nz = cz + (zu[j]-zv[iFrom]); nw = cw + (wu[j]-wv[iFrom]);
#define ADV_CU(j, iFrom)                                                    \
    cx = nx + (xu[j]-xv[iFrom]); cy = ny + (yu[j]-yv[iFrom]);               \
    cz = nz + (zu[j]-zv[iFrom]); cw = nw + (wu[j]-wv[iFrom]);

__global__ __launch_bounds__(NTHREADS, 7)
void ssim_v9_kernel(const float* __restrict__ pred,
                    const float* __restrict__ actual,
                    float* __restrict__ out) {
    const int gtid = blockIdx.x * blockDim.x + threadIdx.x;
    const int W    = gtid >> 5;
    const int lane = gtid & 31;
    const int wid  = threadIdx.x >> 5;

    const int img  = W / NBAND;
    const int band = W - img * NBAND;
    const int r0   = band * BAND_OUT;
    const int c0   = 12 * lane;              // lane 31: cols 372..383

    const float* pX = pred   + (size_t)img * IMG_H * IMG_W + (size_t)r0 * IMG_W + c0;
    const float* pY = actual + (size_t)img * IMG_H * IMG_W + (size_t)r0 * IMG_W + c0;

    u64 X[6], Y[6], Z[6], XY[6];
    #pragma unroll
    for (int i = 0; i < 6; ++i) { X[i]=0; Y[i]=0; Z[i]=0; XY[i]=0; }

    // prologue: admit input rows 0..5
    #pragma unroll 1
    for (int k = 0; k < 6; ++k) {
        float4 x0 = *(const float4*)(pX + (size_t)k*IMG_W);
        float4 x1 = *(const float4*)(pX + (size_t)k*IMG_W + 4);
        float4 x2 = *(const float4*)(pX + (size_t)k*IMG_W + 8);
        float4 y0 = *(const float4*)(pY + (size_t)k*IMG_W);
        float4 y1 = *(const float4*)(pY + (size_t)k*IMG_W + 4);
        float4 y2 = *(const float4*)(pY + (size_t)k*IMG_W + 8);
        ADMIT6(x0,x1,x2,y0,y1,y2);
    }

    // prefetch input row 6
    float4 fx0 = *(const float4*)(pX + (size_t)6*IMG_W);
    float4 fx1 = *(const float4*)(pX + (size_t)6*IMG_W + 4);
    float4 fx2 = *(const float4*)(pX + (size_t)6*IMG_W + 8);
    float4 fy0 = *(const float4*)(pY + (size_t)6*IMG_W);
    float4 fy1 = *(const float4*)(pY + (size_t)6*IMG_W + 4);
    float4 fy2 = *(const float4*)(pY + (size_t)6*IMG_W + 8);

    const float s1   = 1.0f / 49.0f;
    const float covn = 49.0f / 48.0f;
    const u64 c_ns1 = pk2(-s1, -s1);
    const u64 c_kn1 = pk2(2.f * s1 * s1, 2.f * s1 * s1);
    const u64 c_ks2 = pk2(s1 * s1, s1 * s1);
    const u64 c_kcv = pk2(covn * s1, covn * s1);
    const u64 c_kc2 = pk2(2.f * covn * s1, 2.f * covn * s1);
    const u64 c_C1  = pk2(1e-4f, 1e-4f);
    const u64 c_C2  = pk2(9e-4f, 9e-4f);
    const u64 c_one = pk2(1.f, 1.f);
    const float mb  = (lane < 31) ? 1.f : 0.f;
    const u64 mB    = pk2(mb, mb);

    u64 accA = 0, accB = 0;

    #pragma unroll 1
    for (int r = 0; r < BAND_OUT; ++r) {
        // retire-row loads (input row r0+r) — issued early, used at RETIRE6
        float4 rx0 = *(const float4*)(pX);
        float4 rx1 = *(const float4*)(pX + 4);
        float4 rx2 = *(const float4*)(pX + 8);
        float4 ry0 = *(const float4*)(pY);
        float4 ry1 = *(const float4*)(pY + 4);
        float4 ry2 = *(const float4*)(pY + 8);

        // admit prefetched row (input r0+r+6) — window r..r+6 complete
        ADMIT6(fx0,fx1,fx2,fy0,fy1,fy2);

        // prefetch next new row (r0+r+7; last iter loads r0+32, unused)
        {
            const int off = (r < BAND_OUT-1) ? 7 : 6;
            fx0 = *(const float4*)(pX + (size_t)off*IMG_W);
            fx1 = *(const float4*)(pX + (size_t)off*IMG_W + 4);
            fx2 = *(const float4*)(pX + (size_t)off*IMG_W + 8);
            fy0 = *(const float4*)(pY + (size_t)off*IMG_W);
            fy1 = *(const float4*)(pY + (size_t)off*IMG_W + 4);
            fy2 = *(const float4*)(pY + (size_t)off*IMG_W + 8);
        }

        // snapshot vertical sums as scalars
        float xv[12], yv[12], zv[12], wv[12];
        #pragma unroll
        for (int i = 0; i < 6; ++i) {
            upk2(xv[2*i], xv[2*i+1], X[i]);
            upk2(yv[2*i], yv[2*i+1], Y[i]);
            upk2(zv[2*i], zv[2*i+1], Z[i]);
            upk2(wv[2*i], wv[2*i+1], XY[i]);
        }

        // retire row r0+r now — sums ready for next iteration; the
        // horizontal phase below works on the snapshot.
        RETIRE6(rx0,rx1,rx2,ry0,ry1,ry2);

        // W0 = v0..v6 per quantity
        float cx = ((xv[0]+xv[1])+(xv[2]+xv[3]))+((xv[4]+xv[5])+xv[6]);
        float cy = ((yv[0]+yv[1])+(yv[2]+yv[3]))+((yv[4]+yv[5])+yv[6]);
        float cz = ((zv[0]+zv[1])+(zv[2]+zv[3]))+((zv[4]+zv[5])+zv[6]);
        float cw = ((wv[0]+wv[1])+(wv[2]+wv[3]))+((wv[4]+wv[5])+wv[6]);
        float nx, ny, nz, nw;

        // pair (W0,W1)
        ADV_N(7, 0);
        SSIM_PAIR(pk2(cx,nx), pk2(cy,ny), pk2(cz,nz), pk2(cw,nw), c_one, accA);
        ADV_C(8, 1);
        // pair (W2,W3)
        ADV_N(9, 2);
        SSIM_PAIR(pk2(cx,nx), pk2(cy,ny), pk2(cz,nz), pk2(cw,nw), c_one, accA);
        ADV_C(10, 3);
        // pair (W4,W5)
        ADV_N(11, 4);
        SSIM_PAIR(pk2(cx,nx), pk2(cy,ny), pk2(cz,nz), pk2(cw,nw), c_one, accA);

        // neighbor tail v12..v17 (lane+1's v0..v5)
        float xu[6], yu[6], zu[6], wu[6];
        #pragma unroll
        for (int j = 0; j < 6; ++j) {
            xu[j] = __shfl_down_sync(0xffffffffu, xv[j], 1);
            yu[j] = __shfl_down_sync(0xffffffffu, yv[j], 1);
            zu[j] = __shfl_down_sync(0xffffffffu, zv[j], 1);
            wu[j] = __shfl_down_sync(0xffffffffu, wv[j], 1);
        }

        ADV_CU(0, 5);            // W6
        // pair (W6,W7)
        ADV_NU(1, 6);
        SSIM_PAIR(pk2(cx,nx), pk2(cy,ny), pk2(cz,nz), pk2(cw,nw), mB, accB);
        ADV_CU(2, 7);            // W8
        // pair (W8,W9)
        ADV_NU(3, 8);
        SSIM_PAIR(pk2(cx,nx), pk2(cy,ny), pk2(cz,nz), pk2(cw,nw), mB, accB);
        ADV_CU(4, 9);            // W10
        // pair (W10,W11)
        ADV_NU(5, 10);
        SSIM_PAIR(pk2(cx,nx), pk2(cy,ny), pk2(cz,nz), pk2(cw,nw), mB, accB);

        pX += IMG_W;  pY += IMG_W;
    }

    // lane-local total, deterministic warp reduction
    float a0, a1, b0, b1;
    upk2(a0, a1, accA); upk2(b0, b1, accB);
    float acc = (a0 + a1) + (b0 + b1);
    #pragma unroll
    for (int off = 16; off > 0; off >>= 1)
        acc += __shfl_xor_sync(0xffffffffu, acc, off);

    // CTA (2 warps) reduction, deterministic
    __shared__ float warp_sums[2];
    __shared__ unsigned int s_last;
    if (lane == 0) warp_sums[wid] = acc;
    __syncthreads();
    if (threadIdx.x == 0) {
        g_cta[blockIdx.x] = warp_sums[0] + warp_sums[1];
        __threadfence();
        unsigned int old = atomicAdd(&g_done, 1u);
        s_last = (old == NCTA - 1) ? 1u : 0u;
    }
    __syncthreads();

    // last CTA: deterministic fixed-order reduction of 896 partials
    if (s_last) {
        __shared__ float red[NTHREADS];
        const int t = threadIdx.x;
        float c = 0.f;
        #pragma unroll
        for (int i = 0; i < NCTA / NTHREADS; ++i)    // 14 slots, fixed order
            c += g_cta[t + i * NTHREADS];
        red[t] = c;
        __syncthreads();
        #pragma unroll
        for (int s = NTHREADS / 2; s > 0; s >>= 1) {
            if (t < s) red[t] += red[t + s];
            __syncthreads();
        }
        if (t == 0) {
            out[0] = red[0] * (1.0f / ((float)NIMG * (float)OUT_W * (float)OUT_H));
            g_done = 0;   // reset for graph replay
        }
    }
}

extern "C" void kernel_launch(void* const* d_in, const int* in_sizes, int n_in,
                              void* d_out, int out_size) {
    const float* pred   = (const float*)d_in[0];
    const float* actual = (const float*)d_in[1];
    float* out = (float*)d_out;

    ssim_v9_kernel<<<NCTA, NTHREADS>>>(pred, actual, out);
}